// round 15
// baseline (speedup 1.0000x reference)
#include <cuda_runtime.h>
#include <cuda_fp16.h>
#include <cstdint>

// ---------------- problem constants ----------------
#define NN     30000          // nodes
#define FF     1040           // features
#define EE     240000         // raw edges
#define GG     64             // graphs
#define HH     8              // heads
#define DD     130            // head dim
#define LL     3              // blocks

// GEMM padding
#define MPAD   30080          // 235 * 128
#define KPAD   1088           // 17  * 64
#define NPAD   1152           // 9   * 128
#define NCHUNK 17             // KPAD / 64

// ---------------- device scratch (static, no allocs) ----------------
__device__ __half g_x16 [(size_t)MPAD * KPAD];   // layer-0 A operand (padded fp16)
__device__ __half g_hA16[(size_t)MPAD * KPAD];   // h ping (padded fp16)
__device__ __half g_hB16[(size_t)MPAD * KPAD];   // h pong (padded fp16)
__device__ __half g_xh16[(size_t)NN * FF];       // GEMM output, compact fp16
__device__ __half g_W16 [(size_t)LL * NPAD * KPAD];
__device__ float g_as  [NN * HH];
__device__ float g_ad  [NN * HH];
__device__ float g_aw  [(size_t)(EE + NN) * HH];
__device__ int   g_rowptr[NN + 1];
__device__ int   g_cursor[NN];
__device__ int   g_col[EE + NN];
__device__ int   g_deg[NN];
__device__ float g_pooled[GG * FF];
__device__ float g_bnscale[LL * FF];
__device__ float g_bnshift[LL * FF];

// ---------------- PTX helpers (baseline PTX, valid at compute_103) ----------------
__device__ __forceinline__ uint32_t smem_u32(const void* p) {
    uint32_t a;
    asm("{ .reg .u64 t; cvta.to.shared.u64 t, %1; cvt.u32.u64 %0, t; }" : "=r"(a) : "l"(p));
    return a;
}

__device__ __forceinline__ void cp_async16(uint32_t smem_dst, const void* gmem_src) {
    asm volatile("cp.async.cg.shared.global [%0], [%1], 16;"
                 :: "r"(smem_dst), "l"(gmem_src) : "memory");
}
#define CP_COMMIT() asm volatile("cp.async.commit_group;" ::: "memory")

__device__ __forceinline__ void ldm_x4(uint32_t* r, uint32_t addr) {
    asm volatile("ldmatrix.sync.aligned.m8n8.x4.shared.b16 {%0,%1,%2,%3}, [%4];"
                 : "=r"(r[0]), "=r"(r[1]), "=r"(r[2]), "=r"(r[3]) : "r"(addr));
}

__device__ __forceinline__ void mma16816(float* c, const uint32_t* a, const uint32_t* b) {
    asm volatile(
        "mma.sync.aligned.m16n8k16.row.col.f32.f16.f16.f32 "
        "{%0,%1,%2,%3}, {%4,%5,%6,%7}, {%8,%9}, {%0,%1,%2,%3};"
        : "+f"(c[0]), "+f"(c[1]), "+f"(c[2]), "+f"(c[3])
        : "r"(a[0]), "r"(a[1]), "r"(a[2]), "r"(a[3]), "r"(b[0]), "r"(b[1]));
}

// swizzled tile address: tile rows x 128B (64 fp16); c16 = 16B column 0..7
__device__ __forceinline__ uint32_t tile_addr(int row, int c16) {
    return (uint32_t)((row * 8 + (c16 ^ (row & 7))) << 4);
}

// ---------------- CSR build ----------------
__global__ void k_init_deg(int* deg, int n) {
    int i = blockIdx.x * blockDim.x + threadIdx.x;
    if (i < n) deg[i] = 1;  // self loop
}

__global__ void k_hist(const int* __restrict__ dst, int* deg, int e) {
    int i = blockIdx.x * blockDim.x + threadIdx.x;
    if (i < e) atomicAdd(&deg[dst[i]], 1);
}

__global__ void k_scan(const int* __restrict__ deg, int* __restrict__ rowptr, int n) {
    __shared__ int sh[1024];
    __shared__ int carry_s;
    int tid = threadIdx.x;
    if (tid == 0) { carry_s = 0; rowptr[0] = 0; }
    __syncthreads();
    for (int base = 0; base < n; base += 1024) {
        int v = (base + tid < n) ? deg[base + tid] : 0;
        sh[tid] = v;
        __syncthreads();
        for (int off = 1; off < 1024; off <<= 1) {
            int t = (tid >= off) ? sh[tid - off] : 0;
            __syncthreads();
            sh[tid] += t;
            __syncthreads();
        }
        if (base + tid < n) rowptr[base + tid + 1] = carry_s + sh[tid];
        __syncthreads();
        if (tid == 0) carry_s += sh[1023];
        __syncthreads();
    }
}

__global__ void k_copy_cursor(const int* __restrict__ rowptr, int* cursor, int n) {
    int i = blockIdx.x * blockDim.x + threadIdx.x;
    if (i < n) cursor[i] = rowptr[i];
}

__global__ void k_scatter(const int* __restrict__ src, const int* __restrict__ dst,
                          int* cursor, int* col, int e, int n) {
    int i = blockIdx.x * blockDim.x + threadIdx.x;
    if (i >= e + n) return;
    int s, d;
    if (i < e) { s = src[i]; d = dst[i]; }
    else       { s = i - e; d = i - e; }
    int pos = atomicAdd(&cursor[d], 1);
    col[pos] = s;
}

// ---------------- converters / init ----------------
// Zero only the pad region of a padded fp16 buffer:
//   all rows: cols [FF, KPAD) ; rows [NN, MPAD): cols [0, FF)
#define PADW ((KPAD - FF) / 8)          // 6 uint4 per row
#define ZP_COLPAD (MPAD * PADW)         // 180480
#define ZP_ROWPAD ((MPAD - NN) * (FF / 8))  // 10400
__global__ void k_zeropad(__half* p) {
    int idx = blockIdx.x * blockDim.x + threadIdx.x;
    uint4 z = make_uint4(0, 0, 0, 0);
    if (idx < ZP_COLPAD) {
        int row = idx / PADW, c = idx % PADW;
        *((uint4*)(p + (size_t)row * KPAD + FF) + c) = z;
    } else {
        int i2 = idx - ZP_COLPAD;
        if (i2 < ZP_ROWPAD) {
            int row = NN + i2 / (FF / 8), c = i2 % (FF / 8);
            *((uint4*)(p + (size_t)row * KPAD) + c) = z;
        }
    }
}

// x: [NN,FF] f32 -> padded [MPAD,KPAD] fp16, zero pad.
__global__ void __launch_bounds__(256)
k_convX(const float* __restrict__ src, __half* __restrict__ dst) {
    int idx = blockIdx.x * blockDim.x + threadIdx.x;   // over MPAD * (KPAD/8)
    int row = idx / (KPAD / 8);
    int c8  = idx % (KPAD / 8);
    if (row >= MPAD) return;
    int col = c8 * 8;
    float v[8];
    if (row < NN && col < FF) {
        const float4* s = (const float4*)(src + (size_t)row * FF + col);
        float4 a = s[0], b = s[1];
        v[0] = a.x; v[1] = a.y; v[2] = a.z; v[3] = a.w;
        v[4] = b.x; v[5] = b.y; v[6] = b.z; v[7] = b.w;
    } else {
#pragma unroll
        for (int j = 0; j < 8; j++) v[j] = 0.f;
    }
    __half h8[8];
#pragma unroll
    for (int j = 0; j < 8; j++) h8[j] = __float2half_rn(v[j]);
    *(uint4*)(dst + (size_t)row * KPAD + col) = *(const uint4*)&h8[0];
}

// W: [L,FF(k),FF(j)] f32 -> transposed padded [L,NPAD(j),KPAD(k)] fp16.
__global__ void k_convW(const float* __restrict__ W, __half* __restrict__ Wo) {
    __shared__ float t[32][33];
    int l  = blockIdx.z;
    int k0 = blockIdx.x * 32, j0 = blockIdx.y * 32;
    const float* Wl = W + (size_t)l * FF * FF;
#pragma unroll
    for (int i = 0; i < 32; i += 8) {
        int k = k0 + threadIdx.y + i, j = j0 + threadIdx.x;
        t[threadIdx.y + i][threadIdx.x] = (k < FF && j < FF) ? Wl[(size_t)k * FF + j] : 0.f;
    }
    __syncthreads();
    __half* wl = Wo + (size_t)l * NPAD * KPAD;
#pragma unroll
    for (int i = 0; i < 32; i += 8) {
        int j = j0 + threadIdx.y + i, k = k0 + threadIdx.x;
        wl[(size_t)j * KPAD + k] = __float2half_rn(t[threadIdx.x][threadIdx.y + i]);
    }
}

// BN folded: out = z*scale + shift, with b_att absorbed.
__global__ void k_bnprep(const float* __restrict__ gamma, const float* __restrict__ beta,
                         const float* __restrict__ rmean, const float* __restrict__ rvar,
                         const float* __restrict__ b_att,
                         float* __restrict__ scale, float* __restrict__ shift) {
    int i = blockIdx.x * blockDim.x + threadIdx.x;
    if (i >= LL * FF) return;
    float inv = rsqrtf(rvar[i] + 1e-5f);
    float sc = gamma[i] * inv;
    scale[i] = sc;
    shift[i] = beta[i] - rmean[i] * sc + b_att[i] * sc;
}

// ---------------- mma.sync fp16 single-pass GEMM: xh = A @ W^T ----------------
// CTA tile 128x128, 128 threads (4 warps, warp tile 64x64). K chunks of 64,
// 2-stage cp.async. SMEM stage (32KB): A (16KB) | B (16KB). 2 CTAs/SM.
#define TBA      16384
#define TBB      16384
#define ST_BYTES (TBA + TBB)

__device__ __forceinline__ void load_stage(const __half* __restrict__ A,
                                           const __half* __restrict__ B,
                                           size_t rowA, size_t rowB, int col0,
                                           uint32_t st, int tid) {
#pragma unroll
    for (int it = 0; it < 8; it++) {           // A: 128 rows x 8 c16 = 1024
        int idx = it * 128 + tid;
        int row = idx >> 3, c = idx & 7;
        cp_async16(st + tile_addr(row, c), A + (rowA + row) * (size_t)KPAD + col0 + c * 8);
    }
#pragma unroll
    for (int it = 0; it < 8; it++) {           // B: 128 rows x 8 c16 = 1024
        int idx = it * 128 + tid;
        int row = idx >> 3, c = idx & 7;
        cp_async16(st + TBA + tile_addr(row, c), B + (rowB + row) * (size_t)KPAD + col0 + c * 8);
    }
}

extern __shared__ char dynsm[];

__global__ void __launch_bounds__(128, 2)
k_gemm(const __half* __restrict__ A, const __half* __restrict__ B,
       __half* __restrict__ C16) {
    uint32_t sb = smem_u32(dynsm);
    const int tid  = threadIdx.x;
    const int lane = tid & 31;
    const int warp = tid >> 5;
    const int m_off = (warp >> 1) * 64;   // 0,64
    const int n_off = (warp & 1) * 64;    // 0,64
    const size_t rowA = (size_t)blockIdx.y * 128;
    const size_t rowB = (size_t)blockIdx.x * 128;

    const int a_dr = (lane & 7) + ((lane >> 3) & 1) * 8;
    const int a_dc = lane >> 4;            // 0/1
    const int b_dr = (lane & 7) + (lane >> 4) * 8;
    const int b_dc = (lane >> 3) & 1;      // 0/1

    float acc[4][8][4];
#pragma unroll
    for (int mt = 0; mt < 4; mt++)
#pragma unroll
        for (int ng = 0; ng < 8; ng++)
#pragma unroll
            for (int q = 0; q < 4; q++) acc[mt][ng][q] = 0.f;

    load_stage(A, B, rowA, rowB, 0, sb, tid);
    CP_COMMIT();

    for (int kt = 0; kt < NCHUNK; kt++) {
        if (kt + 1 < NCHUNK) {
            load_stage(A, B, rowA, rowB, (kt + 1) * 64,
                       sb + (uint32_t)((kt + 1) & 1) * ST_BYTES, tid);
            CP_COMMIT();
            asm volatile("cp.async.wait_group 1;" ::: "memory");
        } else {
            asm volatile("cp.async.wait_group 0;" ::: "memory");
        }
        __syncthreads();

        uint32_t st = sb + (uint32_t)(kt & 1) * ST_BYTES;
#pragma unroll
        for (int ks = 0; ks < 4; ks++) {
            uint32_t a[4][4];
#pragma unroll
            for (int mt = 0; mt < 4; mt++)
                ldm_x4(a[mt], st + tile_addr(m_off + mt * 16 + a_dr, 2 * ks + a_dc));
            uint32_t b[4][4];
#pragma unroll
            for (int bg = 0; bg < 4; bg++)
                ldm_x4(b[bg], st + TBA + tile_addr(n_off + bg * 16 + b_dr, 2 * ks + b_dc));
#pragma unroll
            for (int mt = 0; mt < 4; mt++)
#pragma unroll
                for (int ng = 0; ng < 8; ng++)
                    mma16816(acc[mt][ng], a[mt], &b[ng >> 1][(ng & 1) * 2]);
        }
        __syncthreads();
    }

    // epilogue: two 64-row passes through a 33KB smem bounce (stride 129)
    float* sbuf = (float*)dynsm;
    const int g  = lane >> 2;
    const int tq = lane & 3;
    const int colg = blockIdx.x * 128 + tid;
#pragma unroll
    for (int half = 0; half < 2; half++) {
        __syncthreads();
        if ((warp >> 1) == half) {
#pragma unroll
            for (int mt = 0; mt < 4; mt++)
#pragma unroll
                for (int ng = 0; ng < 8; ng++) {
                    int r0 = mt * 16 + g;            // within this 64-row half
                    int c0 = n_off + ng * 8 + tq * 2;
                    sbuf[r0 * 129 + c0]           = acc[mt][ng][0];
                    sbuf[r0 * 129 + c0 + 1]       = acc[mt][ng][1];
                    sbuf[(r0 + 8) * 129 + c0]     = acc[mt][ng][2];
                    sbuf[(r0 + 8) * 129 + c0 + 1] = acc[mt][ng][3];
                }
        }
        __syncthreads();
        int gM = blockIdx.y * 128 + half * 64;
        if (colg < FF) {
#pragma unroll 4
            for (int p = 0; p < 64; p++) {
                int gr = gM + p;
                if (gr < NN)
                    C16[(size_t)gr * FF + colg] = __float2half_rn(sbuf[p * 129 + tid]);
            }
        }
    }
}

// ---------------- alpha_src / alpha_dst from xh (fp16, vectorized) ----------------
__global__ void __launch_bounds__(256)
k_alpha(const __half* __restrict__ xh, const float* __restrict__ a_src,
        const float* __restrict__ a_dst, float* __restrict__ as_o,
        float* __restrict__ ad_o) {
    int n = blockIdx.x;
    int h = threadIdx.x >> 5;
    int lane = threadIdx.x & 31;
    // offsets h*DD are even (DD=130) => half2/float2 aligned
    const __half2* xr2 = (const __half2*)(xh + (size_t)n * FF + h * DD);  // 65 half2
    const float2*  av2 = (const float2*)(a_src + h * DD);
    const float2*  bv2 = (const float2*)(a_dst + h * DD);
    float s1 = 0.f, s2 = 0.f;
#pragma unroll
    for (int d2 = lane; d2 < 65; d2 += 32) {
        float2 f = __half22float2(__ldg(&xr2[d2]));
        float2 a = __ldg(&av2[d2]);
        float2 b = __ldg(&bv2[d2]);
        s1 += f.x * a.x + f.y * a.y;
        s2 += f.x * b.x + f.y * b.y;
    }
#pragma unroll
    for (int o = 16; o; o >>= 1) {
        s1 += __shfl_xor_sync(0xffffffffu, s1, o);
        s2 += __shfl_xor_sync(0xffffffffu, s2, o);
    }
    if (lane == 0) { as_o[n * HH + h] = s1; ad_o[n * HH + h] = s2; }
}

// ---------------- per-dst softmax -> edge weights ----------------
// Warp per node; first-edge logits cached in registers (R14 win).
__global__ void __launch_bounds__(128)
k_edgew(const float* __restrict__ as_, const float* __restrict__ ad_,
        const int* __restrict__ rowptr, const int* __restrict__ col,
        float* __restrict__ aw, int n) {
    int i = blockIdx.x * 4 + (threadIdx.x >> 5);
    if (i >= n) return;
    int lane = threadIdx.x & 31;
    int row = rowptr[i], deg = rowptr[i + 1] - row;

    float ad8[HH];
#pragma unroll
    for (int h = 0; h < HH; h++) ad8[h] = __ldg(&ad_[i * HH + h]);

    const bool have = lane < deg;
    float v0[HH];
    if (have) {
        int s = __ldg(&col[row + lane]);
#pragma unroll
        for (int h = 0; h < HH; h++) {
            float v = __ldg(&as_[s * HH + h]) + ad8[h];
            v0[h] = v > 0.f ? v : 0.2f * v;
        }
    }

    float m[HH];
#pragma unroll
    for (int h = 0; h < HH; h++) m[h] = have ? v0[h] : -1e30f;
    for (int e = lane + 32; e < deg; e += 32) {          // rare: deg > 32
        int s = __ldg(&col[row + e]);
#pragma unroll
        for (int h = 0; h < HH; h++) {
            float v = __ldg(&as_[s * HH + h]) + ad8[h];
            v = v > 0.f ? v : 0.2f * v;
            m[h] = fmaxf(m[h], v);
        }
    }
#pragma unroll
    for (int h = 0; h < HH; h++)
#pragma unroll
        for (int o = 16; o; o >>= 1) m[h] = fmaxf(m[h], __shfl_xor_sync(0xffffffffu, m[h], o));

    float sm[HH];
#pragma unroll
    for (int h = 0; h < HH; h++) sm[h] = have ? expf(v0[h] - m[h]) : 0.f;
    for (int e = lane + 32; e < deg; e += 32) {
        int s = __ldg(&col[row + e]);
#pragma unroll
        for (int h = 0; h < HH; h++) {
            float v = __ldg(&as_[s * HH + h]) + ad8[h];
            v = v > 0.f ? v : 0.2f * v;
            sm[h] += expf(v - m[h]);
        }
    }
#pragma unroll
    for (int h = 0; h < HH; h++)
#pragma unroll
        for (int o = 16; o; o >>= 1) sm[h] += __shfl_xor_sync(0xffffffffu, sm[h], o);

    float inv[HH];
#pragma unroll
    for (int h = 0; h < HH; h++) inv[h] = 1.f / sm[h];

    if (have) {
        float* wr = aw + (size_t)(row + lane) * HH;
#pragma unroll
        for (int h = 0; h < HH; h++) wr[h] = expf(v0[h] - m[h]) * inv[h];
    }
    for (int e = lane + 32; e < deg; e += 32) {
        int s = __ldg(&col[row + e]);
        float* wr = aw + (size_t)(row + e) * HH;
#pragma unroll
        for (int h = 0; h < HH; h++) {
            float v = __ldg(&as_[s * HH + h]) + ad8[h];
            v = v > 0.f ? v : 0.2f * v;
            wr[h] = expf(v - m[h]) * inv[h];
        }
    }
}

// ---------------- gather-aggregate + residual + BN + ReLU (fp16 in/out) ----------------
// 160 threads; threads 0..129 own one 8-wide (uint4) feature chunk.
// col + all 8 weights staged to smem once (kills col/aw from the hot chain),
// then feature gather runs with 1-ahead prefetch (addresses smem-resident).
__global__ void __launch_bounds__(160)
k_agg(const __half* __restrict__ xh, const float* __restrict__ aw,
      const int* __restrict__ rowptr, const int* __restrict__ col,
      const __half* __restrict__ prev16, const float* __restrict__ prevf,
      const float* __restrict__ scale, const float* __restrict__ shift,
      __half* __restrict__ hout) {
    __shared__ int   s_col[32];
    __shared__ float s_w[32][HH];

    const int i = blockIdx.x;
    const int tid = threadIdx.x;
    const int row = rowptr[i], end = rowptr[i + 1];
    const int deg = end - row;
    const int cached = deg < 32 ? deg : 32;

    if (tid < 32) {
        if (tid < cached) s_col[tid] = __ldg(&col[row + tid]);
    } else {
        int wt = tid - 32;   // 0..127
        for (int k = wt; k < cached * HH; k += 128)
            s_w[k >> 3][k & 7] = __ldg(&aw[(size_t)(row + (k >> 3)) * HH + (k & 7)]);
    }
    __syncthreads();

    const int c = tid;
    if (c >= 130) return;

    const int j0 = c * 8;
    const int h0 = j0 / DD;
    int split = (h0 + 1) * DD - j0; if (split > 8) split = 8;
    const int h1 = (j0 + 7) / DD;

    float acc[8];
#pragma unroll
    for (int j = 0; j < 8; j++) acc[j] = 0.f;

    const uint4* xv = (const uint4*)xh;

    // main loop over cached edges with 1-ahead prefetch
    uint4 vn = __ldg(&xv[(size_t)s_col[0] * 130 + c]);   // deg >= 1 always (self loop)
    for (int e = 0; e < cached; e++) {
        uint4 v = vn;
        if (e + 1 < cached)
            vn = __ldg(&xv[(size_t)s_col[e + 1] * 130 + c]);
        float a0 = s_w[e][h0];
        float a1 = (h1 != h0) ? s_w[e][h1] : a0;
        const __half2* hp = (const __half2*)&v;
#pragma unroll
        for (int q = 0; q < 4; q++) {
            float2 f = __half22float2(hp[q]);
            float w0 = (2 * q     < split) ? a0 : a1;
            float w1 = (2 * q + 1 < split) ? a0 : a1;
            acc[2 * q]     += w0 * f.x;
            acc[2 * q + 1] += w1 * f.y;
        }
    }

    // rare tail: deg > 32, direct loads
    for (int e = row + 32; e < end; e++) {
        int s = __ldg(&col[e]);
        uint4 v = __ldg(&xv[(size_t)s * 130 + c]);
        float a0 = __ldg(&aw[(size_t)e * HH + h0]);
        float a1 = (h1 != h0) ? __ldg(&aw[(size_t)e * HH + h1]) : a0;
        const __half2* hp = (const __half2*)&v;
#pragma unroll
        for (int q = 0; q < 4; q++) {
            float2 f = __half22float2(hp[q]);
            float w0 = (2 * q     < split) ? a0 : a1;
            float w1 = (2 * q + 1 < split) ? a0 : a1;
            acc[2 * q]     += w0 * f.x;
            acc[2 * q + 1] += w1 * f.y;
        }
    }

    float pv[8];
    if (prevf) {
        const float4* pf = (const float4*)(prevf + (size_t)i * FF + j0);
        float4 x0 = __ldg(pf), x1 = __ldg(pf + 1);
        pv[0] = x0.x; pv[1] = x0.y; pv[2] = x0.z; pv[3] = x0.w;
        pv[4] = x1.x; pv[5] = x1.y; pv[6] = x1.z; pv[7] = x1.w;
    } else if (prev16) {
        uint4 pw = *((const uint4*)(prev16 + (size_t)i * KPAD) + c);
        const __half2* hp = (const __half2*)&pw;
#pragma unroll
        for (int q = 0; q < 4; q++) {
            float2 f = __half22float2(hp[q]);
            pv[2 * q] = f.x; pv[2 * q + 1] = f.y;
        }
    } else {
#pragma unroll
        for (int j = 0; j < 8; j++) pv[j] = 0.f;
    }

    __half outh[8];
#pragma unroll
    for (int j = 0; j < 8; j++) {
        float z = acc[j] + pv[j];
        float o = z * __ldg(&scale[j0 + j]) + __ldg(&shift[j0 + j]);
        outh[j] = __float2half_rn(fmaxf(o, 0.f));
    }
    *((uint4*)(hout + (size_t)i * KPAD) + c) = *(uint4*)outh;
}

// ---------------- pooling ----------------
__device__ __forceinline__ int dlower_bound(const int* a, int n, int key) {
    int lo = 0, hi = n;
    while (lo < hi) {
        int mid = (lo + hi) >> 1;
        if (a[mid] < key) lo = mid + 1; else hi = mid;
    }
    return lo;
}

__global__ void __launch_bounds__(128)
k_pool(const __half* __restrict__ h, const int* __restrict__ batch,
       float* __restrict__ pooled, int n) {
    int g = blockIdx.y;
    int f = blockIdx.x * 128 + threadIdx.x;
    int lo = dlower_bound(batch, n, g);
    int hi = dlower_bound(batch, n, g + 1);
    if (f >= FF) return;
    float s = 0.f;
    for (int nd = lo; nd < hi; nd++) s += __half2float(h[(size_t)nd * KPAD + f]);
    float cnt = (float)((hi - lo) > 0 ? (hi - lo) : 1);
    pooled[g * FF + f] = s / cnt;
}

__global__ void __launch_bounds__(128)
k_out(const float* __restrict__ pooled, const float* __restrict__ Wout,
      const float* __restrict__ bout, float* __restrict__ out) {
    int g = blockIdx.x;
    int tid = threadIdx.x;
    float p0 = 0.f, p1 = 0.f;
    for (int f = tid; f < FF; f += 128) {
        float pv = pooled[g * FF + f];
        p0 += pv * Wout[2 * f];
        p1 += pv * Wout[2 * f + 1];
    }
    __shared__ float s0[128], s1[128];
    s0[tid] = p0; s1[tid] = p1;
    __syncthreads();
    for (int off = 64; off; off >>= 1) {
        if (tid < off) { s0[tid] += s0[tid + off]; s1[tid] += s1[tid + off]; }
        __syncthreads();
    }
    if (tid == 0) {
        out[g * 2 + 0] = s0[0] + bout[0];
        out[g * 2 + 1] = s1[0] + bout[1];
    }
}

// ---------------- launch ----------------
extern "C" void kernel_launch(void* const* d_in, const int* in_sizes, int n_in,
                              void* d_out, int out_size) {
    const float* x      = (const float*)d_in[0];
    const int*   eidx   = (const int*)d_in[1];
    const int*   batch  = (const int*)d_in[2];
    const float* W      = (const float*)d_in[3];
    const float* a_src  = (const float*)d_in[4];
    const float* a_dst  = (const float*)d_in[5];
    const float* b_att  = (const float*)d_in[6];
    const float* gamma  = (const float*)d_in[7];
    const float* beta   = (const float*)d_in[8];
    const float* rmean  = (const float*)d_in[9];
    const float* rvar   = (const float*)d_in[10];
    const float* Wout   = (const float*)d_in[11];
    const float* bout   = (const float*)d_in[12];
    float* out = (float*)d_out;

    const int E = in_sizes[1] / 2;    // 240000
    const int N = in_sizes[0] / FF;   // 30000
    const int E2 = E + N;
    const int* esrc = eidx;
    const int* edst = eidx + E;

    __half *x16, *hA16, *hB16, *xh16, *W16;
    float *as_, *ad_, *aw, *pooled, *bnscale, *bnshift;
    int *rowptr, *cursor, *col, *deg;
    cudaGetSymbolAddress((void**)&x16,     g_x16);
    cudaGetSymbolAddress((void**)&hA16,    g_hA16);
    cudaGetSymbolAddress((void**)&hB16,    g_hB16);
    cudaGetSymbolAddress((void**)&xh16,    g_xh16);
    cudaGetSymbolAddress((void**)&W16,     g_W16);
    cudaGetSymbolAddress((void**)&as_,     g_as);
    cudaGetSymbolAddress((void**)&ad_,     g_ad);
    cudaGetSymbolAddress((void**)&aw,      g_aw);
    cudaGetSymbolAddress((void**)&rowptr,  g_rowptr);
    cudaGetSymbolAddress((void**)&cursor,  g_cursor);
    cudaGetSymbolAddress((void**)&col,     g_col);
    cudaGetSymbolAddress((void**)&deg,     g_deg);
    cudaGetSymbolAddress((void**)&pooled,  g_pooled);
    cudaGetSymbolAddress((void**)&bnscale, g_bnscale);
    cudaGetSymbolAddress((void**)&bnshift, g_bnshift);

    const int GEMM_SMEM = 2 * ST_BYTES;   // 65536 (>= epilogue 33024)
    cudaFuncSetAttribute(k_gemm, cudaFuncAttributeMaxDynamicSharedMemorySize, GEMM_SMEM);

    const int PAD8 = MPAD * KPAD / 8;     // uint4 count of a padded fp16 buffer
    const int ZPN  = ZP_COLPAD + ZP_ROWPAD;
    dim3 ggrid(NPAD / 128, MPAD / 128);   // 9 x 235

    k_convX<<<(PAD8 + 255) / 256, 256>>>(x, x16);                               // 1
    k_convW<<<dim3(KPAD / 32, NPAD / 32, LL), dim3(32, 8)>>>(W, W16);           // 2
    k_gemm<<<ggrid, 128, GEMM_SMEM>>>(x16, W16, xh16);                          // 3
    k_alpha<<<N, 256>>>(xh16, a_src, a_dst, as_, ad_);                          // 4 (captured)

    // CSR build + pad zeroing + BN prep (independent of alpha output)
    k_init_deg<<<(N + 255) / 256, 256>>>(deg, N);
    k_hist<<<(E + 255) / 256, 256>>>(edst, deg, E);
    k_scan<<<1, 1024>>>(deg, rowptr, N);
    k_copy_cursor<<<(N + 255) / 256, 256>>>(rowptr, cursor, N);
    k_scatter<<<(E2 + 255) / 256, 256>>>(esrc, edst, cursor, col, E, N);
    k_zeropad<<<(ZPN + 255) / 256, 256>>>(hA16);
    k_zeropad<<<(ZPN + 255) / 256, 256>>>(hB16);
    k_bnprep<<<(LL * FF + 255) / 256, 256>>>(gamma, beta, rmean, rvar, b_att,
                                             bnscale, bnshift);

    for (int l = 0; l < LL; l++) {
        const __half* prev16 = (l == 2) ? hA16 : nullptr;
        const float*  prevf  = (l == 1) ? x : nullptr;
        __half*       hout   = (l == 0) ? hA16 : (l == 1 ? hB16 : hA16);

        if (l > 0) {
            const __half* Ain = (l == 1) ? hA16 : hB16;
            k_gemm<<<ggrid, 128, GEMM_SMEM>>>(Ain, W16 + (size_t)l * NPAD * KPAD, xh16);
            k_alpha<<<N, 256>>>(xh16, a_src + l * HH * DD, a_dst + l * HH * DD, as_, ad_);
        }
        k_edgew<<<(N + 3) / 4, 128>>>(as_, ad_, rowptr, col, aw, N);
        k_agg<<<N, 160>>>(xh16, aw, rowptr, col, prev16, prevf,
                          bnscale + l * FF, bnshift + l * FF, hout);
    }

    // final h lives in hA16 after block 2
    k_pool<<<dim3((FF + 127) / 128, GG), 128>>>(hA16, batch, pooled, N);
    k_out<<<GG, 128>>>(pooled, Wout, bout, out);
}

// round 16
// speedup vs baseline: 1.0535x; 1.0535x over previous
#include <cuda_runtime.h>
#include <cuda_fp16.h>
#include <cstdint>

// ---------------- problem constants ----------------
#define NN     30000          // nodes
#define FF     1040           // features
#define EE     240000         // raw edges
#define GG     64             // graphs
#define HH     8              // heads
#define DD     130            // head dim
#define LL     3              // blocks

// GEMM padding
#define MPAD   30080          // 235 * 128
#define KPAD   1088           // 17  * 64
#define NPAD   1152           // 9   * 128
#define NCHUNK 17             // KPAD / 64

// ---------------- device scratch (static, no allocs) ----------------
__device__ __half g_x16 [(size_t)MPAD * KPAD];   // layer-0 A operand (padded fp16)
__device__ __half g_hA16[(size_t)MPAD * KPAD];   // h ping (padded fp16)
__device__ __half g_hB16[(size_t)MPAD * KPAD];   // h pong (padded fp16)
__device__ __half g_xh16[(size_t)NN * FF];       // GEMM output, compact fp16
__device__ __half g_W16 [(size_t)LL * NPAD * KPAD];
__device__ float g_as  [NN * HH];
__device__ float g_ad  [NN * HH];
__device__ float g_aw  [(size_t)(EE + NN) * HH];
__device__ int   g_rowptr[NN + 1];
__device__ int   g_cursor[NN];
__device__ int   g_col[EE + NN];
__device__ int   g_deg[NN];
__device__ float g_pooled[GG * FF];
__device__ float g_bnscale[LL * FF];
__device__ float g_bnshift[LL * FF];

// ---------------- PTX helpers (baseline PTX, valid at compute_103) ----------------
__device__ __forceinline__ uint32_t smem_u32(const void* p) {
    uint32_t a;
    asm("{ .reg .u64 t; cvta.to.shared.u64 t, %1; cvt.u32.u64 %0, t; }" : "=r"(a) : "l"(p));
    return a;
}

__device__ __forceinline__ void cp_async16(uint32_t smem_dst, const void* gmem_src) {
    asm volatile("cp.async.cg.shared.global [%0], [%1], 16;"
                 :: "r"(smem_dst), "l"(gmem_src) : "memory");
}
#define CP_COMMIT() asm volatile("cp.async.commit_group;" ::: "memory")

__device__ __forceinline__ void ldm_x4(uint32_t* r, uint32_t addr) {
    asm volatile("ldmatrix.sync.aligned.m8n8.x4.shared.b16 {%0,%1,%2,%3}, [%4];"
                 : "=r"(r[0]), "=r"(r[1]), "=r"(r[2]), "=r"(r[3]) : "r"(addr));
}

// fp16-accumulator HMMA: D,C are 2 b32 regs (4 packed halves)
__device__ __forceinline__ void mma16816_f16(uint32_t* c, const uint32_t* a,
                                             const uint32_t* b) {
    asm volatile(
        "mma.sync.aligned.m16n8k16.row.col.f16.f16.f16.f16 "
        "{%0,%1}, {%2,%3,%4,%5}, {%6,%7}, {%0,%1};"
        : "+r"(c[0]), "+r"(c[1])
        : "r"(a[0]), "r"(a[1]), "r"(a[2]), "r"(a[3]), "r"(b[0]), "r"(b[1]));
}

// swizzled tile address: tile rows x 128B (64 fp16); c16 = 16B column 0..7
__device__ __forceinline__ uint32_t tile_addr(int row, int c16) {
    return (uint32_t)((row * 8 + (c16 ^ (row & 7))) << 4);
}

// ---------------- CSR build ----------------
__global__ void k_init_deg(int* deg, int n) {
    int i = blockIdx.x * blockDim.x + threadIdx.x;
    if (i < n) deg[i] = 1;  // self loop
}

__global__ void k_hist(const int* __restrict__ dst, int* deg, int e) {
    int i = blockIdx.x * blockDim.x + threadIdx.x;
    if (i < e) atomicAdd(&deg[dst[i]], 1);
}

__global__ void k_scan(const int* __restrict__ deg, int* __restrict__ rowptr, int n) {
    __shared__ int sh[1024];
    __shared__ int carry_s;
    int tid = threadIdx.x;
    if (tid == 0) { carry_s = 0; rowptr[0] = 0; }
    __syncthreads();
    for (int base = 0; base < n; base += 1024) {
        int v = (base + tid < n) ? deg[base + tid] : 0;
        sh[tid] = v;
        __syncthreads();
        for (int off = 1; off < 1024; off <<= 1) {
            int t = (tid >= off) ? sh[tid - off] : 0;
            __syncthreads();
            sh[tid] += t;
            __syncthreads();
        }
        if (base + tid < n) rowptr[base + tid + 1] = carry_s + sh[tid];
        __syncthreads();
        if (tid == 0) carry_s += sh[1023];
        __syncthreads();
    }
}

__global__ void k_copy_cursor(const int* __restrict__ rowptr, int* cursor, int n) {
    int i = blockIdx.x * blockDim.x + threadIdx.x;
    if (i < n) cursor[i] = rowptr[i];
}

__global__ void k_scatter(const int* __restrict__ src, const int* __restrict__ dst,
                          int* cursor, int* col, int e, int n) {
    int i = blockIdx.x * blockDim.x + threadIdx.x;
    if (i >= e + n) return;
    int s, d;
    if (i < e) { s = src[i]; d = dst[i]; }
    else       { s = i - e; d = i - e; }
    int pos = atomicAdd(&cursor[d], 1);
    col[pos] = s;
}

// ---------------- converters / init ----------------
// Zero only the pad region of a padded fp16 buffer:
//   all rows: cols [FF, KPAD) ; rows [NN, MPAD): cols [0, FF)
#define PADW ((KPAD - FF) / 8)          // 6 uint4 per row
#define ZP_COLPAD (MPAD * PADW)         // 180480
#define ZP_ROWPAD ((MPAD - NN) * (FF / 8))  // 10400
__global__ void k_zeropad(__half* p) {
    int idx = blockIdx.x * blockDim.x + threadIdx.x;
    uint4 z = make_uint4(0, 0, 0, 0);
    if (idx < ZP_COLPAD) {
        int row = idx / PADW, c = idx % PADW;
        *((uint4*)(p + (size_t)row * KPAD + FF) + c) = z;
    } else {
        int i2 = idx - ZP_COLPAD;
        if (i2 < ZP_ROWPAD) {
            int row = NN + i2 / (FF / 8), c = i2 % (FF / 8);
            *((uint4*)(p + (size_t)row * KPAD) + c) = z;
        }
    }
}

// x: [NN,FF] f32 -> padded [MPAD,KPAD] fp16, zero pad.
__global__ void __launch_bounds__(256)
k_convX(const float* __restrict__ src, __half* __restrict__ dst) {
    int idx = blockIdx.x * blockDim.x + threadIdx.x;   // over MPAD * (KPAD/8)
    int row = idx / (KPAD / 8);
    int c8  = idx % (KPAD / 8);
    if (row >= MPAD) return;
    int col = c8 * 8;
    float v[8];
    if (row < NN && col < FF) {
        const float4* s = (const float4*)(src + (size_t)row * FF + col);
        float4 a = s[0], b = s[1];
        v[0] = a.x; v[1] = a.y; v[2] = a.z; v[3] = a.w;
        v[4] = b.x; v[5] = b.y; v[6] = b.z; v[7] = b.w;
    } else {
#pragma unroll
        for (int j = 0; j < 8; j++) v[j] = 0.f;
    }
    __half h8[8];
#pragma unroll
    for (int j = 0; j < 8; j++) h8[j] = __float2half_rn(v[j]);
    *(uint4*)(dst + (size_t)row * KPAD + col) = *(const uint4*)&h8[0];
}

// W: [L,FF(k),FF(j)] f32 -> transposed padded [L,NPAD(j),KPAD(k)] fp16.
__global__ void k_convW(const float* __restrict__ W, __half* __restrict__ Wo) {
    __shared__ float t[32][33];
    int l  = blockIdx.z;
    int k0 = blockIdx.x * 32, j0 = blockIdx.y * 32;
    const float* Wl = W + (size_t)l * FF * FF;
#pragma unroll
    for (int i = 0; i < 32; i += 8) {
        int k = k0 + threadIdx.y + i, j = j0 + threadIdx.x;
        t[threadIdx.y + i][threadIdx.x] = (k < FF && j < FF) ? Wl[(size_t)k * FF + j] : 0.f;
    }
    __syncthreads();
    __half* wl = Wo + (size_t)l * NPAD * KPAD;
#pragma unroll
    for (int i = 0; i < 32; i += 8) {
        int j = j0 + threadIdx.y + i, k = k0 + threadIdx.x;
        wl[(size_t)j * KPAD + k] = __float2half_rn(t[threadIdx.x][threadIdx.y + i]);
    }
}

// BN folded: out = z*scale + shift, with b_att absorbed.
__global__ void k_bnprep(const float* __restrict__ gamma, const float* __restrict__ beta,
                         const float* __restrict__ rmean, const float* __restrict__ rvar,
                         const float* __restrict__ b_att,
                         float* __restrict__ scale, float* __restrict__ shift) {
    int i = blockIdx.x * blockDim.x + threadIdx.x;
    if (i >= LL * FF) return;
    float inv = rsqrtf(rvar[i] + 1e-5f);
    float sc = gamma[i] * inv;
    scale[i] = sc;
    shift[i] = beta[i] - rmean[i] * sc + b_att[i] * sc;
}

// ---------------- mma.sync fp16 GEMM (fp16 accum): xh = A @ W^T ----------------
// CTA tile 128x128, 128 threads (4 warps, warp tile 64x64). K chunks of 64,
// 2-stage cp.async. SMEM stage (32KB): A (16KB) | B (16KB). 2 CTAs/SM.
// Accumulators are packed half2 (2 regs per mma) -> half the register load.
#define TBA      16384
#define TBB      16384
#define ST_BYTES (TBA + TBB)

__device__ __forceinline__ void load_stage(const __half* __restrict__ A,
                                           const __half* __restrict__ B,
                                           size_t rowA, size_t rowB, int col0,
                                           uint32_t st, int tid) {
#pragma unroll
    for (int it = 0; it < 8; it++) {           // A: 128 rows x 8 c16 = 1024
        int idx = it * 128 + tid;
        int row = idx >> 3, c = idx & 7;
        cp_async16(st + tile_addr(row, c), A + (rowA + row) * (size_t)KPAD + col0 + c * 8);
    }
#pragma unroll
    for (int it = 0; it < 8; it++) {           // B: 128 rows x 8 c16 = 1024
        int idx = it * 128 + tid;
        int row = idx >> 3, c = idx & 7;
        cp_async16(st + TBA + tile_addr(row, c), B + (rowB + row) * (size_t)KPAD + col0 + c * 8);
    }
}

extern __shared__ char dynsm[];

__global__ void __launch_bounds__(128, 2)
k_gemm(const __half* __restrict__ A, const __half* __restrict__ B,
       __half* __restrict__ C16) {
    uint32_t sb = smem_u32(dynsm);
    const int tid  = threadIdx.x;
    const int lane = tid & 31;
    const int warp = tid >> 5;
    const int m_off = (warp >> 1) * 64;   // 0,64
    const int n_off = (warp & 1) * 64;    // 0,64
    const size_t rowA = (size_t)blockIdx.y * 128;
    const size_t rowB = (size_t)blockIdx.x * 128;

    const int a_dr = (lane & 7) + ((lane >> 3) & 1) * 8;
    const int a_dc = lane >> 4;            // 0/1
    const int b_dr = (lane & 7) + (lane >> 4) * 8;
    const int b_dc = (lane >> 3) & 1;      // 0/1

    uint32_t acc[4][8][2];                 // packed half2 accumulators
#pragma unroll
    for (int mt = 0; mt < 4; mt++)
#pragma unroll
        for (int ng = 0; ng < 8; ng++) { acc[mt][ng][0] = 0u; acc[mt][ng][1] = 0u; }

    load_stage(A, B, rowA, rowB, 0, sb, tid);
    CP_COMMIT();

    for (int kt = 0; kt < NCHUNK; kt++) {
        if (kt + 1 < NCHUNK) {
            load_stage(A, B, rowA, rowB, (kt + 1) * 64,
                       sb + (uint32_t)((kt + 1) & 1) * ST_BYTES, tid);
            CP_COMMIT();
            asm volatile("cp.async.wait_group 1;" ::: "memory");
        } else {
            asm volatile("cp.async.wait_group 0;" ::: "memory");
        }
        __syncthreads();

        uint32_t st = sb + (uint32_t)(kt & 1) * ST_BYTES;
#pragma unroll
        for (int ks = 0; ks < 4; ks++) {
            uint32_t a[4][4];
#pragma unroll
            for (int mt = 0; mt < 4; mt++)
                ldm_x4(a[mt], st + tile_addr(m_off + mt * 16 + a_dr, 2 * ks + a_dc));
            uint32_t b[4][4];
#pragma unroll
            for (int bg = 0; bg < 4; bg++)
                ldm_x4(b[bg], st + TBA + tile_addr(n_off + bg * 16 + b_dr, 2 * ks + b_dc));
#pragma unroll
            for (int mt = 0; mt < 4; mt++)
#pragma unroll
                for (int ng = 0; ng < 8; ng++)
                    mma16816_f16(acc[mt][ng], a[mt], &b[ng >> 1][(ng & 1) * 2]);
        }
        __syncthreads();
    }

    // epilogue: two 64-row passes through a 33KB smem bounce (stride 129)
    float* sbuf = (float*)dynsm;
    const int g  = lane >> 2;
    const int tq = lane & 3;
    const int colg = blockIdx.x * 128 + tid;
#pragma unroll
    for (int half = 0; half < 2; half++) {
        __syncthreads();
        if ((warp >> 1) == half) {
#pragma unroll
            for (int mt = 0; mt < 4; mt++)
#pragma unroll
                for (int ng = 0; ng < 8; ng++) {
                    int r0 = mt * 16 + g;            // within this 64-row half
                    int c0 = n_off + ng * 8 + tq * 2;
                    float2 f01 = __half22float2(*(const __half2*)&acc[mt][ng][0]);
                    float2 f23 = __half22float2(*(const __half2*)&acc[mt][ng][1]);
                    sbuf[r0 * 129 + c0]           = f01.x;
                    sbuf[r0 * 129 + c0 + 1]       = f01.y;
                    sbuf[(r0 + 8) * 129 + c0]     = f23.x;
                    sbuf[(r0 + 8) * 129 + c0 + 1] = f23.y;
                }
        }
        __syncthreads();
        int gM = blockIdx.y * 128 + half * 64;
        if (colg < FF) {
#pragma unroll 4
            for (int p = 0; p < 64; p++) {
                int gr = gM + p;
                if (gr < NN)
                    C16[(size_t)gr * FF + colg] = __float2half_rn(sbuf[p * 129 + tid]);
            }
        }
    }
}

// ---------------- alpha_src / alpha_dst from xh (fp16, vectorized) ----------------
__global__ void __launch_bounds__(256)
k_alpha(const __half* __restrict__ xh, const float* __restrict__ a_src,
        const float* __restrict__ a_dst, float* __restrict__ as_o,
        float* __restrict__ ad_o) {
    int n = blockIdx.x;
    int h = threadIdx.x >> 5;
    int lane = threadIdx.x & 31;
    // offsets h*DD are even (DD=130) => half2/float2 aligned
    const __half2* xr2 = (const __half2*)(xh + (size_t)n * FF + h * DD);  // 65 half2
    const float2*  av2 = (const float2*)(a_src + h * DD);
    const float2*  bv2 = (const float2*)(a_dst + h * DD);
    float s1 = 0.f, s2 = 0.f;
#pragma unroll
    for (int d2 = lane; d2 < 65; d2 += 32) {
        float2 f = __half22float2(__ldg(&xr2[d2]));
        float2 a = __ldg(&av2[d2]);
        float2 b = __ldg(&bv2[d2]);
        s1 += f.x * a.x + f.y * a.y;
        s2 += f.x * b.x + f.y * b.y;
    }
#pragma unroll
    for (int o = 16; o; o >>= 1) {
        s1 += __shfl_xor_sync(0xffffffffu, s1, o);
        s2 += __shfl_xor_sync(0xffffffffu, s2, o);
    }
    if (lane == 0) { as_o[n * HH + h] = s1; ad_o[n * HH + h] = s2; }
}

// ---------------- per-dst softmax -> edge weights ----------------
// Warp per node; first-edge logits cached in registers (R14 win).
__global__ void __launch_bounds__(128)
k_edgew(const float* __restrict__ as_, const float* __restrict__ ad_,
        const int* __restrict__ rowptr, const int* __restrict__ col,
        float* __restrict__ aw, int n) {
    int i = blockIdx.x * 4 + (threadIdx.x >> 5);
    if (i >= n) return;
    int lane = threadIdx.x & 31;
    int row = rowptr[i], deg = rowptr[i + 1] - row;

    float ad8[HH];
#pragma unroll
    for (int h = 0; h < HH; h++) ad8[h] = __ldg(&ad_[i * HH + h]);

    const bool have = lane < deg;
    float v0[HH];
    if (have) {
        int s = __ldg(&col[row + lane]);
#pragma unroll
        for (int h = 0; h < HH; h++) {
            float v = __ldg(&as_[s * HH + h]) + ad8[h];
            v0[h] = v > 0.f ? v : 0.2f * v;
        }
    }

    float m[HH];
#pragma unroll
    for (int h = 0; h < HH; h++) m[h] = have ? v0[h] : -1e30f;
    for (int e = lane + 32; e < deg; e += 32) {          // rare: deg > 32
        int s = __ldg(&col[row + e]);
#pragma unroll
        for (int h = 0; h < HH; h++) {
            float v = __ldg(&as_[s * HH + h]) + ad8[h];
            v = v > 0.f ? v : 0.2f * v;
            m[h] = fmaxf(m[h], v);
        }
    }
#pragma unroll
    for (int h = 0; h < HH; h++)
#pragma unroll
        for (int o = 16; o; o >>= 1) m[h] = fmaxf(m[h], __shfl_xor_sync(0xffffffffu, m[h], o));

    float sm[HH];
#pragma unroll
    for (int h = 0; h < HH; h++) sm[h] = have ? expf(v0[h] - m[h]) : 0.f;
    for (int e = lane + 32; e < deg; e += 32) {
        int s = __ldg(&col[row + e]);
#pragma unroll
        for (int h = 0; h < HH; h++) {
            float v = __ldg(&as_[s * HH + h]) + ad8[h];
            v = v > 0.f ? v : 0.2f * v;
            sm[h] += expf(v - m[h]);
        }
    }
#pragma unroll
    for (int h = 0; h < HH; h++)
#pragma unroll
        for (int o = 16; o; o >>= 1) sm[h] += __shfl_xor_sync(0xffffffffu, sm[h], o);

    float inv[HH];
#pragma unroll
    for (int h = 0; h < HH; h++) inv[h] = 1.f / sm[h];

    if (have) {
        float* wr = aw + (size_t)(row + lane) * HH;
#pragma unroll
        for (int h = 0; h < HH; h++) wr[h] = expf(v0[h] - m[h]) * inv[h];
    }
    for (int e = lane + 32; e < deg; e += 32) {
        int s = __ldg(&col[row + e]);
        float* wr = aw + (size_t)(row + e) * HH;
#pragma unroll
        for (int h = 0; h < HH; h++) {
            float v = __ldg(&as_[s * HH + h]) + ad8[h];
            v = v > 0.f ? v : 0.2f * v;
            wr[h] = expf(v - m[h]) * inv[h];
        }
    }
}

// ---------------- gather-aggregate + residual + BN + ReLU (fp16 in/out) ----------------
// 160 threads; threads 0..129 each own one 8-wide (uint4) feature chunk.
// (R14 direct-load form — R15's smem staging regressed.)
__global__ void __launch_bounds__(160)
k_agg(const __half* __restrict__ xh, const float* __restrict__ aw,
      const int* __restrict__ rowptr, const int* __restrict__ col,
      const __half* __restrict__ prev16, const float* __restrict__ prevf,
      const float* __restrict__ scale, const float* __restrict__ shift,
      __half* __restrict__ hout) {
    int i = blockIdx.x;
    int c = threadIdx.x;
    if (c >= 130) return;
    int row = rowptr[i], end = rowptr[i + 1];

    const int j0 = c * 8;
    const int h0 = j0 / DD;
    int split = (h0 + 1) * DD - j0; if (split > 8) split = 8;
    const int h1 = (j0 + 7) / DD;

    float acc[8];
#pragma unroll
    for (int j = 0; j < 8; j++) acc[j] = 0.f;

    const uint4* xv = (const uint4*)xh;
    for (int e = row; e < end; e++) {
        int s = __ldg(&col[e]);
        uint4 v = __ldg(&xv[(size_t)s * 130 + c]);
        float a0 = __ldg(&aw[(size_t)e * HH + h0]);
        float a1 = (h1 != h0) ? __ldg(&aw[(size_t)e * HH + h1]) : a0;
        const __half2* hp = (const __half2*)&v;
#pragma unroll
        for (int q = 0; q < 4; q++) {
            float2 f = __half22float2(hp[q]);
            float w0 = (2 * q     < split) ? a0 : a1;
            float w1 = (2 * q + 1 < split) ? a0 : a1;
            acc[2 * q]     += w0 * f.x;
            acc[2 * q + 1] += w1 * f.y;
        }
    }

    float pv[8];
    if (prevf) {
        const float4* pf = (const float4*)(prevf + (size_t)i * FF + j0);
        float4 x0 = __ldg(pf), x1 = __ldg(pf + 1);
        pv[0] = x0.x; pv[1] = x0.y; pv[2] = x0.z; pv[3] = x0.w;
        pv[4] = x1.x; pv[5] = x1.y; pv[6] = x1.z; pv[7] = x1.w;
    } else if (prev16) {
        uint4 pw = *((const uint4*)(prev16 + (size_t)i * KPAD) + c);
        const __half2* hp = (const __half2*)&pw;
#pragma unroll
        for (int q = 0; q < 4; q++) {
            float2 f = __half22float2(hp[q]);
            pv[2 * q] = f.x; pv[2 * q + 1] = f.y;
        }
    } else {
#pragma unroll
        for (int j = 0; j < 8; j++) pv[j] = 0.f;
    }

    __half outh[8];
#pragma unroll
    for (int j = 0; j < 8; j++) {
        float z = acc[j] + pv[j];
        float o = z * __ldg(&scale[j0 + j]) + __ldg(&shift[j0 + j]);
        outh[j] = __float2half_rn(fmaxf(o, 0.f));
    }
    *((uint4*)(hout + (size_t)i * KPAD) + c) = *(uint4*)outh;
}

// ---------------- pooling ----------------
__device__ __forceinline__ int dlower_bound(const int* a, int n, int key) {
    int lo = 0, hi = n;
    while (lo < hi) {
        int mid = (lo + hi) >> 1;
        if (a[mid] < key) lo = mid + 1; else hi = mid;
    }
    return lo;
}

__global__ void __launch_bounds__(128)
k_pool(const __half* __restrict__ h, const int* __restrict__ batch,
       float* __restrict__ pooled, int n) {
    int g = blockIdx.y;
    int f = blockIdx.x * 128 + threadIdx.x;
    int lo = dlower_bound(batch, n, g);
    int hi = dlower_bound(batch, n, g + 1);
    if (f >= FF) return;
    float s = 0.f;
    for (int nd = lo; nd < hi; nd++) s += __half2float(h[(size_t)nd * KPAD + f]);
    float cnt = (float)((hi - lo) > 0 ? (hi - lo) : 1);
    pooled[g * FF + f] = s / cnt;
}

__global__ void __launch_bounds__(128)
k_out(const float* __restrict__ pooled, const float* __restrict__ Wout,
      const float* __restrict__ bout, float* __restrict__ out) {
    int g = blockIdx.x;
    int tid = threadIdx.x;
    float p0 = 0.f, p1 = 0.f;
    for (int f = tid; f < FF; f += 128) {
        float pv = pooled[g * FF + f];
        p0 += pv * Wout[2 * f];
        p1 += pv * Wout[2 * f + 1];
    }
    __shared__ float s0[128], s1[128];
    s0[tid] = p0; s1[tid] = p1;
    __syncthreads();
    for (int off = 64; off; off >>= 1) {
        if (tid < off) { s0[tid] += s0[tid + off]; s1[tid] += s1[tid + off]; }
        __syncthreads();
    }
    if (tid == 0) {
        out[g * 2 + 0] = s0[0] + bout[0];
        out[g * 2 + 1] = s1[0] + bout[1];
    }
}

// ---------------- launch ----------------
extern "C" void kernel_launch(void* const* d_in, const int* in_sizes, int n_in,
                              void* d_out, int out_size) {
    const float* x      = (const float*)d_in[0];
    const int*   eidx   = (const int*)d_in[1];
    const int*   batch  = (const int*)d_in[2];
    const float* W      = (const float*)d_in[3];
    const float* a_src  = (const float*)d_in[4];
    const float* a_dst  = (const float*)d_in[5];
    const float* b_att  = (const float*)d_in[6];
    const float* gamma  = (const float*)d_in[7];
    const float* beta   = (const float*)d_in[8];
    const float* rmean  = (const float*)d_in[9];
    const float* rvar   = (const float*)d_in[10];
    const float* Wout   = (const float*)d_in[11];
    const float* bout   = (const float*)d_in[12];
    float* out = (float*)d_out;

    const int E = in_sizes[1] / 2;    // 240000
    const int N = in_sizes[0] / FF;   // 30000
    const int E2 = E + N;
    const int* esrc = eidx;
    const int* edst = eidx + E;

    __half *x16, *hA16, *hB16, *xh16, *W16;
    float *as_, *ad_, *aw, *pooled, *bnscale, *bnshift;
    int *rowptr, *cursor, *col, *deg;
    cudaGetSymbolAddress((void**)&x16,     g_x16);
    cudaGetSymbolAddress((void**)&hA16,    g_hA16);
    cudaGetSymbolAddress((void**)&hB16,    g_hB16);
    cudaGetSymbolAddress((void**)&xh16,    g_xh16);
    cudaGetSymbolAddress((void**)&W16,     g_W16);
    cudaGetSymbolAddress((void**)&as_,     g_as);
    cudaGetSymbolAddress((void**)&ad_,     g_ad);
    cudaGetSymbolAddress((void**)&aw,      g_aw);
    cudaGetSymbolAddress((void**)&rowptr,  g_rowptr);
    cudaGetSymbolAddress((void**)&cursor,  g_cursor);
    cudaGetSymbolAddress((void**)&col,     g_col);
    cudaGetSymbolAddress((void**)&deg,     g_deg);
    cudaGetSymbolAddress((void**)&pooled,  g_pooled);
    cudaGetSymbolAddress((void**)&bnscale, g_bnscale);
    cudaGetSymbolAddress((void**)&bnshift, g_bnshift);

    const int GEMM_SMEM = 2 * ST_BYTES;   // 65536 (>= epilogue 33024)
    cudaFuncSetAttribute(k_gemm, cudaFuncAttributeMaxDynamicSharedMemorySize, GEMM_SMEM);

    const int PAD8 = MPAD * KPAD / 8;     // uint4 count of a padded fp16 buffer
    const int ZPN  = ZP_COLPAD + ZP_ROWPAD;
    dim3 ggrid(NPAD / 128, MPAD / 128);   // 9 x 235

    k_convX<<<(PAD8 + 255) / 256, 256>>>(x, x16);                               // 1
    k_convW<<<dim3(KPAD / 32, NPAD / 32, LL), dim3(32, 8)>>>(W, W16);           // 2
    k_gemm<<<ggrid, 128, GEMM_SMEM>>>(x16, W16, xh16);                          // 3 (captured window)
    k_alpha<<<N, 256>>>(xh16, a_src, a_dst, as_, ad_);                          // 4

    // CSR build + pad zeroing + BN prep (independent of alpha output)
    k_init_deg<<<(N + 255) / 256, 256>>>(deg, N);
    k_hist<<<(E + 255) / 256, 256>>>(edst, deg, E);
    k_scan<<<1, 1024>>>(deg, rowptr, N);
    k_copy_cursor<<<(N + 255) / 256, 256>>>(rowptr, cursor, N);
    k_scatter<<<(E2 + 255) / 256, 256>>>(esrc, edst, cursor, col, E, N);
    k_zeropad<<<(ZPN + 255) / 256, 256>>>(hA16);
    k_zeropad<<<(ZPN + 255) / 256, 256>>>(hB16);
    k_bnprep<<<(LL * FF + 255) / 256, 256>>>(gamma, beta, rmean, rvar, b_att,
                                             bnscale, bnshift);

    for (int l = 0; l < LL; l++) {
        const __half* prev16 = (l == 2) ? hA16 : nullptr;
        const float*  prevf  = (l == 1) ? x : nullptr;
        __half*       hout   = (l == 0) ? hA16 : (l == 1 ? hB16 : hA16);

        if (l > 0) {
            const __half* Ain = (l == 1) ? hA16 : hB16;
            k_gemm<<<ggrid, 128, GEMM_SMEM>>>(Ain, W16 + (size_t)l * NPAD * KPAD, xh16);
            k_alpha<<<N, 256>>>(xh16, a_src + l * HH * DD, a_dst + l * HH * DD, as_, ad_);
        }
        k_edgew<<<(N + 3) / 4, 128>>>(as_, ad_, rowptr, col, aw, N);
        k_agg<<<N, 160>>>(xh16, aw, rowptr, col, prev16, prevf,
                          bnscale + l * FF, bnshift + l * FF, hout);
    }

    // final h lives in hA16 after block 2
    k_pool<<<dim3((FF + 127) / 128, GG), 128>>>(hA16, batch, pooled, N);
    k_out<<<GG, 128>>>(pooled, Wout, bout, out);
}